// round 6
// baseline (speedup 1.0000x reference)
#include <cuda_runtime.h>
#include <cuda_bf16.h>
#include <math.h>
#include <stdint.h>

#define NPIX 16384
#define CDIM 128
#define NB 2
#define NV 6
#define BVI 12
#define WW 128

typedef uint16_t u16;
typedef uint32_t u32;

// ---------------- scratch planes (hi/lo bf16) ----------------
__device__ __align__(16) u16 g_xm1h[(size_t)BVI * 256 * NPIX];
__device__ __align__(16) u16 g_xm1l[(size_t)BVI * 256 * NPIX];
__device__ __align__(16) u16 g_hgh [(size_t)BVI * 256 * NPIX];
__device__ __align__(16) u16 g_hgl [(size_t)BVI * 256 * NPIX];
__device__ __align__(16) u16 g_m1h [(size_t)BVI * 128 * NPIX];
__device__ __align__(16) u16 g_m1l [(size_t)BVI * 128 * NPIX];
__device__ __align__(16) u16 g_dwh [(size_t)BVI * 128 * NPIX];
__device__ __align__(16) u16 g_dwl [(size_t)BVI * 128 * NPIX];
__device__ __align__(16) u16 g_mrgh[(size_t)BVI * 128 * NPIX];
__device__ __align__(16) u16 g_mrgl[(size_t)BVI * 128 * NPIX];
__device__ __align__(16) u16 g_g1h [(size_t)BVI * 128 * NPIX];
__device__ __align__(16) u16 g_g1l [(size_t)BVI * 128 * NPIX];
__device__ __align__(16) u16 g_g2h [(size_t)BVI * 128 * NPIX];
__device__ __align__(16) u16 g_g2l [(size_t)BVI * 128 * NPIX];
__device__ __align__(16) u16 g_plh [(size_t)NB * 128 * NPIX];
__device__ __align__(16) u16 g_pll [(size_t)NB * 128 * NPIX];
// weight planes
__device__ __align__(16) u16 g_wm1h[128 * 256], g_wm1l[128 * 256];
__device__ __align__(16) u16 g_wm2h[128 * 128], g_wm2l[128 * 128];
__device__ __align__(16) u16 g_wgh [256 * 128], g_wgl [256 * 128];
__device__ __align__(16) u16 g_wgbh[256 * 128], g_wgbl[256 * 128];
__device__ __align__(16) u16 g_wuph[128 * 128], g_wupl[128 * 128];
// fp32 scratch
__device__ float g_alp[(size_t)BVI * NPIX];
__device__ float g_u  [(size_t)NB * 128 * NPIX];

__device__ __forceinline__ float gelu_exact(float x) {
    return 0.5f * x * (1.0f + erff(x * 0.70710678118654752f));
}
__device__ __forceinline__ u32 smem_u32(const void* p) {
    return (u32)__cvta_generic_to_shared(p);
}
// fp32 pair -> bf16x2 hi + bf16x2 lo(residual); low halfword = first element
__device__ __forceinline__ void split_pack(float v0, float v1, u32& hi, u32& lo) {
    asm("cvt.rn.bf16x2.f32 %0, %1, %2;" : "=r"(hi) : "f"(v1), "f"(v0));
    float r0 = v0 - __uint_as_float(hi << 16);
    float r1 = v1 - __uint_as_float(hi & 0xffff0000u);
    asm("cvt.rn.bf16x2.f32 %0, %1, %2;" : "=r"(lo) : "f"(r1), "f"(r0));
}
__device__ __forceinline__ float bf_lo(u32 w) { return __uint_as_float(w << 16); }
__device__ __forceinline__ float bf_hi(u32 w) { return __uint_as_float(w & 0xffff0000u); }
__device__ __forceinline__ float bf1(u16 w) { return __uint_as_float((u32)w << 16); }

__device__ __forceinline__ void ldm_x4(u32* r, u32 addr) {
    asm volatile("ldmatrix.sync.aligned.m8n8.x4.shared.b16 {%0,%1,%2,%3}, [%4];"
                 : "=r"(r[0]), "=r"(r[1]), "=r"(r[2]), "=r"(r[3]) : "r"(addr));
}
__device__ __forceinline__ void ldm_x4t(u32* r, u32 addr) {
    asm volatile("ldmatrix.sync.aligned.m8n8.x4.trans.shared.b16 {%0,%1,%2,%3}, [%4];"
                 : "=r"(r[0]), "=r"(r[1]), "=r"(r[2]), "=r"(r[3]) : "r"(addr));
}
__device__ __forceinline__ void mma_bf16(float* d, const u32* a, const u32* b) {
    asm volatile(
        "mma.sync.aligned.m16n8k16.row.col.f32.bf16.bf16.f32 "
        "{%0,%1,%2,%3}, {%4,%5,%6,%7}, {%8,%9}, {%0,%1,%2,%3};"
        : "+f"(d[0]), "+f"(d[1]), "+f"(d[2]), "+f"(d[3])
        : "r"(a[0]), "r"(a[1]), "r"(a[2]), "r"(a[3]), "r"(b[0]), "r"(b[1]));
}
__device__ __forceinline__ void cpasync16(u32 dst, const void* src) {
    asm volatile("cp.async.cg.shared.global [%0], [%1], 16;" :: "r"(dst), "l"(src));
}
__device__ __forceinline__ void cp_commit() {
    asm volatile("cp.async.commit_group;" ::: "memory");
}

// ---------------- GEMM: Out[m, pix] = (Wh+Wl)[m,:] @ (Bh+Bl)[:, pix] ----------------
// 3-pass split bf16 MMA: hi*hi + hi*lo + lo*hi. cp.async double-buffered B.
// EPI: 0 bias-only; 1 gelu(+bias); 2 bias+residual. OUTF32: write fp32 else hi/lo planes.
constexpr int KC = 64;
constexpr int A_PITCH = 144;   // 128B row + 16B pad
constexpr int B_PITCH = 272;   // 256B row + 16B pad
constexpr int A_PLANE = 128 * A_PITCH;          // 18432
constexpr int B_PLANE = KC * B_PITCH;           // 17408
constexpr int B_STAGE = 2 * B_PLANE;            // hi+lo 34816
constexpr int GSMEM = 2 * A_PLANE + 2 * B_STAGE; // 106496

template <int KTOT, int MTOT, int EPI, bool OUTF32>
__global__ __launch_bounds__(256, 2) void gemm_mma(
    const u16* __restrict__ Bh_g, const u16* __restrict__ Bl_g,
    const u16* __restrict__ Wh_g, const u16* __restrict__ Wl_g,
    const float* __restrict__ Bias, const float* __restrict__ Res,
    u16* __restrict__ OutH, u16* __restrict__ OutL, float* __restrict__ OutF)
{
    extern __shared__ __align__(16) char sm[];
    const u32 a_sm = smem_u32(sm);
    const u32 b_sm = a_sm + 2 * A_PLANE;

    const int img = blockIdx.z;
    const int p0  = blockIdx.x * 128;
    const int m0  = blockIdx.y * 128;
    const int tid = threadIdx.x;
    const int lane = tid & 31, wid = tid >> 5;
    const int wm = wid >> 2, wn = wid & 3;

    float acc[4][4][4];
#pragma unroll
    for (int i = 0; i < 4; i++)
#pragma unroll
        for (int j = 0; j < 4; j++)
#pragma unroll
            for (int q = 0; q < 4; q++) acc[i][j][q] = 0.f;

    constexpr int NCH = KTOT / KC;

    // ---- copy lambdas ----
    auto copyB = [&](int c, int s) {
        const size_t base = ((size_t)img * KTOT + c * KC) * NPIX + p0;
#pragma unroll
        for (int i = 0; i < 8; i++) {
            int idx = tid + i * 256;
            int plane = idx >> 10, rem = idx & 1023;
            int row = rem >> 4, seg = rem & 15;
            const u16* src = (plane ? Bl_g : Bh_g) + base + (size_t)row * NPIX + seg * 8;
            u32 dst = b_sm + s * B_STAGE + plane * B_PLANE + row * B_PITCH + seg * 16;
            cpasync16(dst, src);
        }
    };
    auto copyA = [&](int c) {
        const size_t base = (size_t)m0 * KTOT + c * KC;
#pragma unroll
        for (int i = 0; i < 8; i++) {
            int idx = tid + i * 256;
            int plane = idx >> 10, rem = idx & 1023;
            int row = rem >> 3, seg = rem & 7;
            const u16* src = (plane ? Wl_g : Wh_g) + base + (size_t)row * KTOT + seg * 8;
            u32 dst = a_sm + plane * A_PLANE + row * A_PITCH + seg * 16;
            cpasync16(dst, src);
        }
    };

    // ldmatrix per-thread address components
    const int lr  = lane & 7;
    const int lth = (lane >> 3) & 1;
    const int ltv = lane >> 4;
    const u32 a_row = (u32)(wm * 64 + lth * 8 + lr);

    // prologue
    copyB(0, 0); cp_commit();
    copyA(0);    cp_commit();

#pragma unroll 1
    for (int c = 0; c < NCH; c++) {
        const int s = c & 1;
        if (c + 1 < NCH) {
            copyB(c + 1, s ^ 1); cp_commit();
            asm volatile("cp.async.wait_group 1;" ::: "memory");
        } else {
            asm volatile("cp.async.wait_group 0;" ::: "memory");
        }
        __syncthreads();

        const u32 ah = a_sm, al = a_sm + A_PLANE;
        const u32 bh = b_sm + s * B_STAGE, bl = bh + B_PLANE;

#pragma unroll
        for (int kk = 0; kk < KC / 16; kk++) {
            u32 af[4][4];
            u32 bfh[4][2], bfl[4][2];
            const u32 a_off = a_row * A_PITCH + kk * 32 + ltv * 16;
            const u32 b_off = (u32)(kk * 16 + lth * 8 + lr) * B_PITCH + wn * 64 + ltv * 16;
#pragma unroll
            for (int mf = 0; mf < 4; mf++)
                ldm_x4(af[mf], ah + a_off + mf * 16 * A_PITCH);
#pragma unroll
            for (int nh = 0; nh < 2; nh++) {
                u32 r[4];
                ldm_x4t(r, bh + b_off + nh * 32);
                bfh[nh * 2][0] = r[0]; bfh[nh * 2][1] = r[1];
                bfh[nh * 2 + 1][0] = r[2]; bfh[nh * 2 + 1][1] = r[3];
            }
#pragma unroll
            for (int mf = 0; mf < 4; mf++)
#pragma unroll
                for (int nf = 0; nf < 4; nf++)
                    mma_bf16(acc[mf][nf], af[mf], bfh[nf]);
#pragma unroll
            for (int nh = 0; nh < 2; nh++) {
                u32 r[4];
                ldm_x4t(r, bl + b_off + nh * 32);
                bfl[nh * 2][0] = r[0]; bfl[nh * 2][1] = r[1];
                bfl[nh * 2 + 1][0] = r[2]; bfl[nh * 2 + 1][1] = r[3];
            }
#pragma unroll
            for (int mf = 0; mf < 4; mf++)
#pragma unroll
                for (int nf = 0; nf < 4; nf++)
                    mma_bf16(acc[mf][nf], af[mf], bfl[nf]);
#pragma unroll
            for (int mf = 0; mf < 4; mf++)
                ldm_x4(af[mf], al + a_off + mf * 16 * A_PITCH);
#pragma unroll
            for (int mf = 0; mf < 4; mf++)
#pragma unroll
                for (int nf = 0; nf < 4; nf++)
                    mma_bf16(acc[mf][nf], af[mf], bfh[nf]);
        }
        __syncthreads();
        if (c + 1 < NCH) { copyA(c + 1); cp_commit(); }
    }

    // epilogue
    const int g = lane >> 2, tg = lane & 3;
#pragma unroll
    for (int mf = 0; mf < 4; mf++) {
#pragma unroll
        for (int half = 0; half < 2; half++) {
            const int m = m0 + wm * 64 + mf * 16 + half * 8 + g;
            const float bias = Bias ? Bias[m] : 0.f;
            const size_t rowb = ((size_t)img * MTOT + m) * NPIX;
            const float* resrow = (EPI == 2) ? &Res[((size_t)img * CDIM + m) * NPIX] : nullptr;
#pragma unroll
            for (int nf = 0; nf < 4; nf++) {
                const int px = p0 + wn * 32 + nf * 8 + 2 * tg;
                float v0 = acc[mf][nf][half * 2 + 0] + bias;
                float v1 = acc[mf][nf][half * 2 + 1] + bias;
                if (EPI == 1) { v0 = gelu_exact(v0); v1 = gelu_exact(v1); }
                if (EPI == 2) { v0 += resrow[px]; v1 += resrow[px + 1]; }
                if (OUTF32) {
                    *reinterpret_cast<float2*>(&OutF[rowb + px]) = make_float2(v0, v1);
                } else {
                    u32 hi, lo;
                    split_pack(v0, v1, hi, lo);
                    const size_t hw = (rowb + px) >> 1;
                    reinterpret_cast<u32*>(OutH)[hw] = hi;
                    reinterpret_cast<u32*>(OutL)[hw] = lo;
                }
            }
        }
    }
}

// ---------------- prep: weights fp32 -> hi/lo planes ----------------
__global__ void prep_w(const float* __restrict__ w, u16* __restrict__ wh,
                       u16* __restrict__ wl, int n)
{
    int i = blockIdx.x * 256 + threadIdx.x;
    if (i < n) {
        float v = w[i];
        u32 hb = __float_as_uint(v) & 0xffff0000u;
        float hf = __uint_as_float(hb);
        // round-to-nearest bf16
        __nv_bfloat16 h = __float2bfloat16(v);
        hf = __bfloat162float(h);
        wh[i] = (u16)(__float_as_uint(hf) >> 16);
        __nv_bfloat16 l = __float2bfloat16(v - hf);
        wl[i] = (u16)(__float_as_uint(__bfloat162float(l)) >> 16);
        (void)hb;
    }
}

// ---------------- prep: feats|prj -> xm1 planes [img][256][NPIX] ----------------
__global__ __launch_bounds__(256) void prep_x(
    const float* __restrict__ feats, const float* __restrict__ prj,
    u16* __restrict__ xh, u16* __restrict__ xl)
{
    int k = blockIdx.y, img = blockIdx.z;
    int p4 = (blockIdx.x * 256 + threadIdx.x) * 4;
    const float* src = (k < 128)
        ? feats + ((size_t)img * 128 + k) * NPIX
        : prj   + ((size_t)img * 128 + (k - 128)) * NPIX;
    float4 v = *reinterpret_cast<const float4*>(&src[p4]);
    u32 h0, l0, h1, l1;
    split_pack(v.x, v.y, h0, l0);
    split_pack(v.z, v.w, h1, l1);
    size_t d = (((size_t)img * 256 + k) * NPIX + p4) >> 1;
    reinterpret_cast<uint2*>(xh)[d >> 1] = make_uint2(h0, h1);
    reinterpret_cast<uint2*>(xl)[d >> 1] = make_uint2(l0, l1);
}

// ---------------- depthwise 3x3 + bias + GELU (planes in, planes out) ----------------
__global__ __launch_bounds__(256) void dw3x3_p(
    const u16* __restrict__ inH, const u16* __restrict__ inL,
    const float* __restrict__ wd, const float* __restrict__ bd,
    u16* __restrict__ outH, u16* __restrict__ outL)
{
    int c = blockIdx.y, img = blockIdx.z;
    int pix0 = (blockIdx.x * 256 + threadIdx.x) * 2;
    int h = pix0 >> 7, w0 = pix0 & 127;
    const size_t base = ((size_t)img * 128 + c) * NPIX;
    const u16* pH = inH + base;
    const u16* pL = inL + base;
    float wreg[9];
#pragma unroll
    for (int i = 0; i < 9; i++) wreg[i] = wd[c * 9 + i];
    float s[2] = {bd[c], bd[c]};
#pragma unroll
    for (int ky = 0; ky < 3; ky++) {
        int hh = h + ky - 1;
        if ((unsigned)hh >= 128u) continue;
#pragma unroll
        for (int kx = 0; kx < 3; kx++) {
#pragma unroll
            for (int e = 0; e < 2; e++) {
                int ww = w0 + e + kx - 1;
                if ((unsigned)ww >= 128u) continue;
                int off = hh * WW + ww;
                s[e] = fmaf(wreg[ky * 3 + kx], bf1(pH[off]) + bf1(pL[off]), s[e]);
            }
        }
    }
    float v0 = gelu_exact(s[0]), v1 = gelu_exact(s[1]);
    u32 hi, lo;
    split_pack(v0, v1, hi, lo);
    reinterpret_cast<u32*>(outH)[(base + pix0) >> 1] = hi;
    reinterpret_cast<u32*>(outL)[(base + pix0) >> 1] = lo;
}

// ---------------- minGRU scan over V (planes) ----------------
__global__ __launch_bounds__(256) void gru_scan_p(
    const u16* __restrict__ hgH, const u16* __restrict__ hgL,
    u16* __restrict__ gH, u16* __restrict__ gL)
{
    int c = blockIdx.y, b = blockIdx.z;
    int pix0 = (blockIdx.x * 256 + threadIdx.x) * 2;
    float h0 = 0.f, h1 = 0.f;
#pragma unroll
    for (int v = 0; v < NV; v++) {
        size_t base = (((size_t)(b * NV + v)) * 256 + c) * NPIX + pix0;
        u32 hh = *reinterpret_cast<const u32*>(&hgH[base]);
        u32 hl = *reinterpret_cast<const u32*>(&hgL[base]);
        u32 gh = *reinterpret_cast<const u32*>(&hgH[base + (size_t)128 * NPIX]);
        u32 gl = *reinterpret_cast<const u32*>(&hgL[base + (size_t)128 * NPIX]);
        float hid0 = bf_lo(hh) + bf_lo(hl), hid1 = bf_hi(hh) + bf_hi(hl);
        float gt0  = bf_lo(gh) + bf_lo(gl), gt1  = bf_hi(gh) + bf_hi(gl);
        float z0 = 1.f / (1.f + expf(-gt0));
        float z1 = 1.f / (1.f + expf(-gt1));
        float ht0 = (hid0 >= 0.f) ? (hid0 + 0.5f) : (1.f / (1.f + expf(-hid0)));
        float ht1 = (hid1 >= 0.f) ? (hid1 + 0.5f) : (1.f / (1.f + expf(-hid1)));
        h0 = (1.f - z0) * h0 + z0 * ht0;
        h1 = (1.f - z1) * h1 + z1 * ht1;
        u32 hi, lo;
        split_pack(h0, h1, hi, lo);
        size_t d = ((((size_t)(b * NV + v)) * 128 + c) * NPIX + pix0) >> 1;
        reinterpret_cast<u32*>(gH)[d] = hi;
        reinterpret_cast<u32*>(gL)[d] = lo;
    }
}

// ---------------- alpha: 3x3 conv C->1 (planes in) ----------------
__global__ __launch_bounds__(256) void alpha_p(
    const u16* __restrict__ g2H, const u16* __restrict__ g2L,
    const float* __restrict__ aw, const float* __restrict__ ab,
    float* __restrict__ alpha)
{
    __shared__ float w[1152];
    for (int i = threadIdx.x; i < 1152; i += 256) w[i] = aw[i];
    __syncthreads();
    int img = blockIdx.z;
    int pix = blockIdx.x * 256 + threadIdx.x;
    int h = pix >> 7, x = pix & 127;
    float s = ab[0];
    const size_t base = (size_t)img * 128 * NPIX;
    for (int c = 0; c < 128; c++) {
        const u16* pH = g2H + base + (size_t)c * NPIX;
        const u16* pL = g2L + base + (size_t)c * NPIX;
        const float* wc = w + c * 9;
#pragma unroll
        for (int ky = 0; ky < 3; ky++) {
            int hh = h + ky - 1;
            if ((unsigned)hh >= 128u) continue;
#pragma unroll
            for (int kx = 0; kx < 3; kx++) {
                int ww = x + kx - 1;
                if ((unsigned)ww >= 128u) continue;
                int off = hh * WW + ww;
                s = fmaf(wc[ky * 3 + kx], bf1(pH[off]) + bf1(pL[off]), s);
            }
        }
    }
    alpha[(size_t)img * NPIX + pix] = s;
}

// ---------------- softmax over V + weighted pool (planes in/out) ----------------
__global__ __launch_bounds__(256) void pool_p(
    const u16* __restrict__ g2H, const u16* __restrict__ g2L,
    const float* __restrict__ alpha, u16* __restrict__ plH, u16* __restrict__ plL)
{
    int b = blockIdx.z;
    int pix0 = (blockIdx.x * 256 + threadIdx.x) * 2;
    float a0[NV], a1[NV];
    float mx0 = -1e30f, mx1 = -1e30f;
#pragma unroll
    for (int v = 0; v < NV; v++) {
        float2 av = *reinterpret_cast<const float2*>(&alpha[(size_t)(b * NV + v) * NPIX + pix0]);
        a0[v] = av.x; a1[v] = av.y;
        mx0 = fmaxf(mx0, av.x); mx1 = fmaxf(mx1, av.y);
    }
    float sum0 = 0.f, sum1 = 0.f;
#pragma unroll
    for (int v = 0; v < NV; v++) {
        a0[v] = expf(a0[v] - mx0); sum0 += a0[v];
        a1[v] = expf(a1[v] - mx1); sum1 += a1[v];
    }
    float inv0 = 1.f / sum0, inv1 = 1.f / sum1;
#pragma unroll
    for (int v = 0; v < NV; v++) { a0[v] *= inv0; a1[v] *= inv1; }
    for (int c = 0; c < 128; c++) {
        float s0 = 0.f, s1 = 0.f;
#pragma unroll
        for (int v = 0; v < NV; v++) {
            size_t off = (((size_t)(b * NV + v)) * 128 + c) * NPIX + pix0;
            u32 wh = *reinterpret_cast<const u32*>(&g2H[off]);
            u32 wl = *reinterpret_cast<const u32*>(&g2L[off]);
            s0 = fmaf(a0[v], bf_lo(wh) + bf_lo(wl), s0);
            s1 = fmaf(a1[v], bf_hi(wh) + bf_hi(wl), s1);
        }
        u32 hi, lo;
        split_pack(s0, s1, hi, lo);
        size_t d = (((size_t)b * 128 + c) * NPIX + pix0) >> 1;
        reinterpret_cast<u32*>(plH)[d] = hi;
        reinterpret_cast<u32*>(plL)[d] = lo;
    }
}

// ---------------- pixel-shuffle(4) + 3x3 conv 8->3 (512 resize = identity) ----------------
__global__ __launch_bounds__(256) void outc_k(
    const float* __restrict__ u, const float* __restrict__ wt,
    const float* __restrict__ bs, float* __restrict__ out)
{
    __shared__ float w[216];
    if (threadIdx.x < 216) w[threadIdx.x] = wt[threadIdx.x];
    __syncthreads();
    int b = blockIdx.z, co = blockIdx.y;
    int idx = blockIdx.x * 256 + threadIdx.x;
    int y = idx >> 9, x = idx & 511;
    float s = bs[co];
    const float* ub = u + (size_t)b * 128 * NPIX;
#pragma unroll
    for (int ky = 0; ky < 3; ky++) {
        int yy = y + ky - 1;
        if ((unsigned)yy >= 512u) continue;
        int sy = yy & 3, hy = yy >> 2;
#pragma unroll
        for (int kx = 0; kx < 3; kx++) {
            int xx = x + kx - 1;
            if ((unsigned)xx >= 512u) continue;
            int sx = xx & 3, hx = xx >> 2;
            const float* up = ub + (size_t)(sy * 4 + sx) * NPIX + hy * WW + hx;
#pragma unroll
            for (int ci = 0; ci < 8; ci++)
                s = fmaf(w[(co * 8 + ci) * 9 + ky * 3 + kx], up[(size_t)ci * 16 * NPIX], s);
        }
    }
    out[((size_t)b * 3 + co) * (512 * 512) + idx] = s;
}

// ---------------- launch ----------------
extern "C" void kernel_launch(void* const* d_in, const int* in_sizes, int n_in,
                              void* d_out, int out_size)
{
    const float* feats     = (const float*)d_in[0];
    const float* prj       = (const float*)d_in[1];
    const float* merge_w1  = (const float*)d_in[2];
    const float* merge_b1  = (const float*)d_in[3];
    const float* merge_wd  = (const float*)d_in[4];
    const float* merge_bd  = (const float*)d_in[5];
    const float* merge_w2  = (const float*)d_in[6];
    const float* merge_b2  = (const float*)d_in[7];
    const float* gru_w     = (const float*)d_in[8];
    const float* gru_bw    = (const float*)d_in[9];
    const float* alpha_w   = (const float*)d_in[10];
    const float* alpha_b   = (const float*)d_in[11];
    const float* up_w      = (const float*)d_in[12];
    const float* up_b      = (const float*)d_in[13];
    const float* outc_w    = (const float*)d_in[14];
    const float* outc_b    = (const float*)d_in[15];

    u16 *xm1h, *xm1l, *hgh, *hgl, *m1h, *m1l, *dwh, *dwl, *mrgh, *mrgl;
    u16 *g1h, *g1l, *g2h, *g2l, *plh, *pll;
    u16 *wm1h, *wm1l, *wm2h, *wm2l, *wgh, *wgl, *wgbh, *wgbl, *wuph, *wupl;
    float *alp, *ubuf;
    cudaGetSymbolAddress((void**)&xm1h, g_xm1h); cudaGetSymbolAddress((void**)&xm1l, g_xm1l);
    cudaGetSymbolAddress((void**)&hgh,  g_hgh);  cudaGetSymbolAddress((void**)&hgl,  g_hgl);
    cudaGetSymbolAddress((void**)&m1h,  g_m1h);  cudaGetSymbolAddress((void**)&m1l,  g_m1l);
    cudaGetSymbolAddress((void**)&dwh,  g_dwh);  cudaGetSymbolAddress((void**)&dwl,  g_dwl);
    cudaGetSymbolAddress((void**)&mrgh, g_mrgh); cudaGetSymbolAddress((void**)&mrgl, g_mrgl);
    cudaGetSymbolAddress((void**)&g1h,  g_g1h);  cudaGetSymbolAddress((void**)&g1l,  g_g1l);
    cudaGetSymbolAddress((void**)&g2h,  g_g2h);  cudaGetSymbolAddress((void**)&g2l,  g_g2l);
    cudaGetSymbolAddress((void**)&plh,  g_plh);  cudaGetSymbolAddress((void**)&pll,  g_pll);
    cudaGetSymbolAddress((void**)&wm1h, g_wm1h); cudaGetSymbolAddress((void**)&wm1l, g_wm1l);
    cudaGetSymbolAddress((void**)&wm2h, g_wm2h); cudaGetSymbolAddress((void**)&wm2l, g_wm2l);
    cudaGetSymbolAddress((void**)&wgh,  g_wgh);  cudaGetSymbolAddress((void**)&wgl,  g_wgl);
    cudaGetSymbolAddress((void**)&wgbh, g_wgbh); cudaGetSymbolAddress((void**)&wgbl, g_wgbl);
    cudaGetSymbolAddress((void**)&wuph, g_wuph); cudaGetSymbolAddress((void**)&wupl, g_wupl);
    cudaGetSymbolAddress((void**)&alp,  g_alp);  cudaGetSymbolAddress((void**)&ubuf, g_u);

    cudaFuncSetAttribute(gemm_mma<256, 128, 1, false>, cudaFuncAttributeMaxDynamicSharedMemorySize, GSMEM);
    cudaFuncSetAttribute(gemm_mma<128, 128, 2, false>, cudaFuncAttributeMaxDynamicSharedMemorySize, GSMEM);
    cudaFuncSetAttribute(gemm_mma<128, 256, 0, false>, cudaFuncAttributeMaxDynamicSharedMemorySize, GSMEM);
    cudaFuncSetAttribute(gemm_mma<128, 128, 0, true >, cudaFuncAttributeMaxDynamicSharedMemorySize, GSMEM);

    // weight prep (tiny)
    prep_w<<<128, 256>>>(merge_w1, wm1h, wm1l, 128 * 256);
    prep_w<<<64,  256>>>(merge_w2, wm2h, wm2l, 128 * 128);
    prep_w<<<128, 256>>>(gru_w,    wgh,  wgl,  256 * 128);
    prep_w<<<128, 256>>>(gru_bw,   wgbh, wgbl, 256 * 128);
    prep_w<<<64,  256>>>(up_w,     wuph, wupl, 128 * 128);
    // input prep: feats|prj -> [img][256][NPIX] planes
    prep_x<<<dim3(16, 256, BVI), 256>>>(feats, prj, xm1h, xm1l);

    // merge1: 1x1 (2C->C) + GELU
    gemm_mma<256, 128, 1, false><<<dim3(128, 1, BVI), 256, GSMEM>>>(
        xm1h, xm1l, wm1h, wm1l, merge_b1, nullptr, m1h, m1l, nullptr);
    // depthwise 3x3 + GELU
    dw3x3_p<<<dim3(32, 128, BVI), 256>>>(m1h, m1l, merge_wd, merge_bd, dwh, dwl);
    // merge2: 1x1 (C->C) + bias + residual(feats fp32)
    gemm_mma<128, 128, 2, false><<<dim3(128, 1, BVI), 256, GSMEM>>>(
        dwh, dwl, wm2h, wm2l, merge_b2, feats, mrgh, mrgl, nullptr);
    // fwd GRU linear (C->2C)
    gemm_mma<128, 256, 0, false><<<dim3(128, 2, BVI), 256, GSMEM>>>(
        mrgh, mrgl, wgh, wgl, nullptr, nullptr, hgh, hgl, nullptr);
    gru_scan_p<<<dim3(32, 128, NB), 256>>>(hgh, hgl, g1h, g1l);
    // bwd GRU linear (H-flips cancel -> forward scan)
    gemm_mma<128, 256, 0, false><<<dim3(128, 2, BVI), 256, GSMEM>>>(
        g1h, g1l, wgbh, wgbl, nullptr, nullptr, hgh, hgl, nullptr);
    gru_scan_p<<<dim3(32, 128, NB), 256>>>(hgh, hgl, g2h, g2l);
    // alpha conv + softmax pool
    alpha_p<<<dim3(64, 1, BVI), 256>>>(g2h, g2l, alpha_w, alpha_b, alp);
    pool_p<<<dim3(32, 1, NB), 256>>>(g2h, g2l, alp, plh, pll);
    // up 1x1 conv -> fp32 u
    gemm_mma<128, 128, 0, true><<<dim3(128, 1, NB), 256, GSMEM>>>(
        plh, pll, wuph, wupl, up_b, nullptr, nullptr, nullptr, ubuf);
    // pixel shuffle + outc 3x3
    outc_k<<<dim3(1024, 3, NB), 256>>>(ubuf, outc_w, outc_b, (float*)d_out);
}

// round 7
// speedup vs baseline: 1.2547x; 1.2547x over previous
#include <cuda_runtime.h>
#include <cuda_bf16.h>
#include <math.h>
#include <stdint.h>

#define NPIX 16384
#define CDIM 128
#define NB 2
#define NV 6
#define BVI 12
#define WW 128

typedef uint16_t u16;
typedef uint32_t u32;

// ---------------- scratch ----------------
__device__ float g_bufA[(size_t)BVI * CDIM * NPIX];
__device__ float g_bufB[(size_t)BVI * CDIM * NPIX];
__device__ float g_bufC[(size_t)BVI * CDIM * NPIX];
__device__ float g_hg  [(size_t)BVI * 2 * CDIM * NPIX];
__device__ float g_alp [(size_t)BVI * NPIX];
__device__ float g_pool[(size_t)NB * CDIM * NPIX];
__device__ float g_u   [(size_t)NB * CDIM * NPIX];
// weight hi/lo planes (k-major rows)
__device__ __align__(16) u16 g_wm1h[128 * 256], g_wm1l[128 * 256];
__device__ __align__(16) u16 g_wm2h[128 * 128], g_wm2l[128 * 128];
__device__ __align__(16) u16 g_wgh [256 * 128], g_wgl [256 * 128];
__device__ __align__(16) u16 g_wgbh[256 * 128], g_wgbl[256 * 128];
__device__ __align__(16) u16 g_wuph[128 * 128], g_wupl[128 * 128];

__device__ __forceinline__ float gelu_exact(float x) {
    return 0.5f * x * (1.0f + erff(x * 0.70710678118654752f));
}
__device__ __forceinline__ u32 smem_u32(const void* p) {
    return (u32)__cvta_generic_to_shared(p);
}
__device__ __forceinline__ void split_pack(float v0, float v1, u32& hi, u32& lo) {
    asm("cvt.rn.bf16x2.f32 %0, %1, %2;" : "=r"(hi) : "f"(v1), "f"(v0));
    float r0 = v0 - __uint_as_float(hi << 16);
    float r1 = v1 - __uint_as_float(hi & 0xffff0000u);
    asm("cvt.rn.bf16x2.f32 %0, %1, %2;" : "=r"(lo) : "f"(r1), "f"(r0));
}
__device__ __forceinline__ void ldm_x4(u32* r, u32 addr) {
    asm volatile("ldmatrix.sync.aligned.m8n8.x4.shared.b16 {%0,%1,%2,%3}, [%4];"
                 : "=r"(r[0]), "=r"(r[1]), "=r"(r[2]), "=r"(r[3]) : "r"(addr));
}
__device__ __forceinline__ void ldm_x4t(u32* r, u32 addr) {
    asm volatile("ldmatrix.sync.aligned.m8n8.x4.trans.shared.b16 {%0,%1,%2,%3}, [%4];"
                 : "=r"(r[0]), "=r"(r[1]), "=r"(r[2]), "=r"(r[3]) : "r"(addr));
}
__device__ __forceinline__ void mma_bf16(float* d, const u32* a, const u32* b) {
    asm volatile(
        "mma.sync.aligned.m16n8k16.row.col.f32.bf16.bf16.f32 "
        "{%0,%1,%2,%3}, {%4,%5,%6,%7}, {%8,%9}, {%0,%1,%2,%3};"
        : "+f"(d[0]), "+f"(d[1]), "+f"(d[2]), "+f"(d[3])
        : "r"(a[0]), "r"(a[1]), "r"(a[2]), "r"(a[3]), "r"(b[0]), "r"(b[1]));
}
__device__ __forceinline__ void cpasync16(u32 dst, const void* src) {
    asm volatile("cp.async.cg.shared.global [%0], [%1], 16;" :: "r"(dst), "l"(src));
}
__device__ __forceinline__ void cp_commit() {
    asm volatile("cp.async.commit_group;" ::: "memory");
}

// ---------------- GEMM: Out[m,pix] = (Wh+Wl)[m,:] @ X[:,pix], 3-pass split bf16 ----------------
// KC=32 chunks; A = pre-split bf16 planes (cp.async, double-buffered);
// B = fp32 (cp.async staged, double-buffered) -> converted in smem.
constexpr int KC = 32;
constexpr int A_PITCH_B = 80;                  // 64B row + 16 pad
constexpr int A_PLANE_B = 128 * A_PITCH_B;     // 10240
constexpr int A_STAGE_B = 2 * A_PLANE_B;       // hi+lo 20480
constexpr int BF32_PITCH = 528;                // 512B row + 16 pad
constexpr int BF32_STAGE = KC * BF32_PITCH;    // 16896
constexpr int BB_PITCH = 272;                  // 256B row + 16 pad
constexpr int BB_PLANE = KC * BB_PITCH;        // 8704
// layout: A stage0 | A stage1 | Bf32 s0 | Bf32 s1 | B hi | B lo
constexpr int OFF_A0  = 0;
constexpr int OFF_A1  = A_STAGE_B;
constexpr int OFF_F0  = 2 * A_STAGE_B;
constexpr int OFF_F1  = OFF_F0 + BF32_STAGE;
constexpr int OFF_BH  = OFF_F1 + BF32_STAGE;
constexpr int OFF_BL  = OFF_BH + BB_PLANE;
constexpr int GSMEM   = OFF_BL + BB_PLANE;     // 92160

template <int KTOT, int MTOT, int EPI, bool SPLIT>
__global__ __launch_bounds__(256, 2) void gemm_mma(
    const float* __restrict__ X0, const float* __restrict__ X1,
    const u16* __restrict__ Wh_g, const u16* __restrict__ Wl_g,
    const float* __restrict__ Bias, const float* __restrict__ Res,
    float* __restrict__ Out)
{
    extern __shared__ __align__(16) char sm[];
    const u32 sm0 = smem_u32(sm);

    const int img = blockIdx.z;
    const int p0  = blockIdx.x * 128;
    const int m0  = blockIdx.y * 128;
    const int tid = threadIdx.x;
    const int lane = tid & 31, wid = tid >> 5;
    const int wm = wid >> 2, wn = wid & 3;

    float acc[4][4][4];
#pragma unroll
    for (int i = 0; i < 4; i++)
#pragma unroll
        for (int j = 0; j < 4; j++)
#pragma unroll
            for (int q = 0; q < 4; q++) acc[i][j][q] = 0.f;

    constexpr int NCH = KTOT / KC;

    auto copyAB = [&](int c, int s) {
        const int kbase = c * KC;
        // B fp32 chunk
        const float* Xc = X0;
        int kb = kbase;
        if (SPLIT && kbase >= 128) { Xc = X1; kb = kbase - 128; }
        const size_t bbase = ((size_t)img * (SPLIT ? 128 : KTOT) + kb) * NPIX + p0;
        const u32 fdst = sm0 + (s ? OFF_F1 : OFF_F0);
#pragma unroll
        for (int i = 0; i < 4; i++) {
            int idx = tid + i * 256;
            int row = idx >> 5, seg = idx & 31;
            cpasync16(fdst + row * BF32_PITCH + seg * 16,
                      Xc + bbase + (size_t)row * NPIX + seg * 4);
        }
        // A bf16 planes
        const size_t abase = (size_t)m0 * KTOT + kbase;
        const u32 adst = sm0 + (s ? OFF_A1 : OFF_A0);
#pragma unroll
        for (int i = 0; i < 4; i++) {
            int idx = tid + i * 256;
            int plane = idx >> 9, rem = idx & 511;
            int row = rem >> 2, seg = rem & 3;
            const u16* src = (plane ? Wl_g : Wh_g) + abase + (size_t)row * KTOT + seg * 8;
            cpasync16(adst + plane * A_PLANE_B + row * A_PITCH_B + seg * 16, src);
        }
    };

    // ldmatrix per-thread address components
    const int lr  = lane & 7;
    const int lth = (lane >> 3) & 1;
    const int ltv = lane >> 4;
    const u32 a_row = (u32)(wm * 64 + lth * 8 + lr);

    copyAB(0, 0); cp_commit();

#pragma unroll 1
    for (int c = 0; c < NCH; c++) {
        const int s = c & 1;
        __syncthreads();   // prior chunk's MMA reads (A stage s, B bf16) complete
        if (c + 1 < NCH) {
            copyAB(c + 1, s ^ 1); cp_commit();
            asm volatile("cp.async.wait_group 1;" ::: "memory");
        } else {
            asm volatile("cp.async.wait_group 0;" ::: "memory");
        }
        __syncthreads();   // stage s visible to all threads

        // convert B fp32 stage s -> bf16 hi/lo planes
        {
            const char* fsrc = sm + (s ? OFF_F1 : OFF_F0);
#pragma unroll
            for (int i = 0; i < 8; i++) {
                int p = tid + i * 256;          // pair index 0..2047
                int row = p >> 6, cp2 = p & 63;
                float2 v = *reinterpret_cast<const float2*>(fsrc + row * BF32_PITCH + cp2 * 8);
                u32 hi, lo;
                split_pack(v.x, v.y, hi, lo);
                *reinterpret_cast<u32*>(sm + OFF_BH + row * BB_PITCH + cp2 * 4) = hi;
                *reinterpret_cast<u32*>(sm + OFF_BL + row * BB_PITCH + cp2 * 4) = lo;
            }
        }
        __syncthreads();   // bf16 planes ready

        const u32 ah = sm0 + (s ? OFF_A1 : OFF_A0);
        const u32 al = ah + A_PLANE_B;
        const u32 bh = sm0 + OFF_BH, bl = sm0 + OFF_BL;

#pragma unroll
        for (int kk = 0; kk < KC / 16; kk++) {
            u32 af[4][4];
            u32 bfh[4][2], bfl[4][2];
            const u32 a_off = a_row * A_PITCH_B + kk * 32 + ltv * 16;
            const u32 b_off = (u32)(kk * 16 + lth * 8 + lr) * BB_PITCH + wn * 64 + ltv * 16;
#pragma unroll
            for (int mf = 0; mf < 4; mf++)
                ldm_x4(af[mf], ah + a_off + mf * 16 * A_PITCH_B);
#pragma unroll
            for (int nh = 0; nh < 2; nh++) {
                u32 r[4];
                ldm_x4t(r, bh + b_off + nh * 32);
                bfh[nh * 2][0] = r[0]; bfh[nh * 2][1] = r[1];
                bfh[nh * 2 + 1][0] = r[2]; bfh[nh * 2 + 1][1] = r[3];
            }
#pragma unroll
            for (int mf = 0; mf < 4; mf++)
#pragma unroll
                for (int nf = 0; nf < 4; nf++)
                    mma_bf16(acc[mf][nf], af[mf], bfh[nf]);
#pragma unroll
            for (int nh = 0; nh < 2; nh++) {
                u32 r[4];
                ldm_x4t(r, bl + b_off + nh * 32);
                bfl[nh * 2][0] = r[0]; bfl[nh * 2][1] = r[1];
                bfl[nh * 2 + 1][0] = r[2]; bfl[nh * 2 + 1][1] = r[3];
            }
#pragma unroll
            for (int mf = 0; mf < 4; mf++)
#pragma unroll
                for (int nf = 0; nf < 4; nf++)
                    mma_bf16(acc[mf][nf], af[mf], bfl[nf]);
#pragma unroll
            for (int mf = 0; mf < 4; mf++)
                ldm_x4(af[mf], al + a_off + mf * 16 * A_PITCH_B);
#pragma unroll
            for (int mf = 0; mf < 4; mf++)
#pragma unroll
                for (int nf = 0; nf < 4; nf++)
                    mma_bf16(acc[mf][nf], af[mf], bfh[nf]);
        }
    }

    // epilogue
    const int g = lane >> 2, tg = lane & 3;
#pragma unroll
    for (int mf = 0; mf < 4; mf++) {
#pragma unroll
        for (int half = 0; half < 2; half++) {
            const int m = m0 + wm * 64 + mf * 16 + half * 8 + g;
            const float bias = Bias ? Bias[m] : 0.f;
            const size_t rowb = ((size_t)img * MTOT + m) * NPIX;
            const float* resrow = (EPI == 2) ? &Res[((size_t)img * CDIM + m) * NPIX] : nullptr;
#pragma unroll
            for (int nf = 0; nf < 4; nf++) {
                const int px = p0 + wn * 32 + nf * 8 + 2 * tg;
                float v0 = acc[mf][nf][half * 2 + 0] + bias;
                float v1 = acc[mf][nf][half * 2 + 1] + bias;
                if (EPI == 1) { v0 = gelu_exact(v0); v1 = gelu_exact(v1); }
                if (EPI == 2) { v0 += resrow[px]; v1 += resrow[px + 1]; }
                *reinterpret_cast<float2*>(&Out[rowb + px]) = make_float2(v0, v1);
            }
        }
    }
}

// ---------------- fused weight prep: all 5 weight tensors -> hi/lo planes ----------------
__global__ void prep_w_all(
    const float* __restrict__ w1, const float* __restrict__ w2,
    const float* __restrict__ wg, const float* __restrict__ wgb,
    const float* __restrict__ wup,
    u16* __restrict__ w1h, u16* __restrict__ w1l,
    u16* __restrict__ w2h, u16* __restrict__ w2l,
    u16* __restrict__ wgh, u16* __restrict__ wgl,
    u16* __restrict__ wgbh, u16* __restrict__ wgbl,
    u16* __restrict__ wuph, u16* __restrict__ wupl)
{
    int i = blockIdx.x * 256 + threadIdx.x;
    const float* src; u16 *dh, *dl; int off;
    if      (i < 32768)  { src = w1;  dh = w1h;  dl = w1l;  off = i; }
    else if (i < 49152)  { src = w2;  dh = w2h;  dl = w2l;  off = i - 32768; }
    else if (i < 81920)  { src = wg;  dh = wgh;  dl = wgl;  off = i - 49152; }
    else if (i < 114688) { src = wgb; dh = wgbh; dl = wgbl; off = i - 81920; }
    else                 { src = wup; dh = wuph; dl = wupl; off = i - 114688; }
    float v = src[off];
    float hf = __bfloat162float(__float2bfloat16(v));
    dh[off] = (u16)(__float_as_uint(hf) >> 16);
    dl[off] = (u16)(__float_as_uint(__bfloat162float(__float2bfloat16(v - hf))) >> 16);
}

// ---------------- depthwise 3x3 + bias + GELU ----------------
__global__ __launch_bounds__(256) void dw3x3(
    const float* __restrict__ in, const float* __restrict__ wd,
    const float* __restrict__ bd, float* __restrict__ out)
{
    int c = blockIdx.y, img = blockIdx.z;
    int pix = blockIdx.x * 256 + threadIdx.x;
    int h = pix >> 7, w = pix & 127;
    const float* p = in + ((size_t)img * CDIM + c) * NPIX;
    float s = bd[c];
#pragma unroll
    for (int ky = 0; ky < 3; ky++) {
        int hh = h + ky - 1;
        if ((unsigned)hh >= 128u) continue;
#pragma unroll
        for (int kx = 0; kx < 3; kx++) {
            int ww = w + kx - 1;
            if ((unsigned)ww >= 128u) continue;
            s = fmaf(wd[c * 9 + ky * 3 + kx], p[hh * WW + ww], s);
        }
    }
    out[((size_t)img * CDIM + c) * NPIX + pix] = gelu_exact(s);
}

// ---------------- minGRU scan over V (both passes forward: H-flips cancel) ----------------
__global__ __launch_bounds__(256) void gru_scan(const float* __restrict__ hg, float* __restrict__ g)
{
    int c = blockIdx.y, b = blockIdx.z;
    int pix = blockIdx.x * 256 + threadIdx.x;
    float h = 0.f;
#pragma unroll
    for (int v = 0; v < NV; v++) {
        size_t base = (((size_t)(b * NV + v)) * 2 * CDIM + c) * NPIX + pix;
        float hid = hg[base];
        float gt  = hg[base + (size_t)CDIM * NPIX];
        float z  = 1.f / (1.f + expf(-gt));
        float ht = (hid >= 0.f) ? (hid + 0.5f) : (1.f / (1.f + expf(-hid)));
        h = (1.f - z) * h + z * ht;
        g[(((size_t)(b * NV + v)) * CDIM + c) * NPIX + pix] = h;
    }
}

// ---------------- alpha: 3x3 conv C->1 ----------------
__global__ __launch_bounds__(256) void alpha_conv(
    const float* __restrict__ g2, const float* __restrict__ aw,
    const float* __restrict__ ab, float* __restrict__ alpha)
{
    __shared__ float w[1152];
    for (int i = threadIdx.x; i < 1152; i += 256) w[i] = aw[i];
    __syncthreads();
    int img = blockIdx.z;
    int pix = blockIdx.x * 256 + threadIdx.x;
    int h = pix >> 7, x = pix & 127;
    float s = ab[0];
    const float* base = g2 + (size_t)img * CDIM * NPIX;
    for (int c = 0; c < CDIM; c++) {
        const float* p  = base + (size_t)c * NPIX;
        const float* wc = w + c * 9;
#pragma unroll
        for (int ky = 0; ky < 3; ky++) {
            int hh = h + ky - 1;
            if ((unsigned)hh >= 128u) continue;
#pragma unroll
            for (int kx = 0; kx < 3; kx++) {
                int ww = x + kx - 1;
                if ((unsigned)ww >= 128u) continue;
                s = fmaf(wc[ky * 3 + kx], p[hh * WW + ww], s);
            }
        }
    }
    alpha[(size_t)img * NPIX + pix] = s;
}

// ---------------- softmax over V + weighted pool ----------------
__global__ __launch_bounds__(256) void pool_k(
    const float* __restrict__ g2, const float* __restrict__ alpha, float* __restrict__ out)
{
    int b = blockIdx.z;
    int pix = blockIdx.x * 256 + threadIdx.x;
    float a[NV];
    float mx = -1e30f;
#pragma unroll
    for (int v = 0; v < NV; v++) {
        a[v] = alpha[(size_t)(b * NV + v) * NPIX + pix];
        mx = fmaxf(mx, a[v]);
    }
    float sum = 0.f;
#pragma unroll
    for (int v = 0; v < NV; v++) { a[v] = expf(a[v] - mx); sum += a[v]; }
    float inv = 1.f / sum;
#pragma unroll
    for (int v = 0; v < NV; v++) a[v] *= inv;
    for (int c = 0; c < CDIM; c++) {
        float s = 0.f;
#pragma unroll
        for (int v = 0; v < NV; v++)
            s = fmaf(a[v], g2[(((size_t)(b * NV + v)) * CDIM + c) * NPIX + pix], s);
        out[((size_t)b * CDIM + c) * NPIX + pix] = s;
    }
}

// ---------------- pixel-shuffle(4) + 3x3 conv 8->3 (512->512 resize = identity) ----------------
__global__ __launch_bounds__(256) void outc_k(
    const float* __restrict__ u, const float* __restrict__ wt,
    const float* __restrict__ bs, float* __restrict__ out)
{
    __shared__ float w[216];
    if (threadIdx.x < 216) w[threadIdx.x] = wt[threadIdx.x];
    __syncthreads();
    int b = blockIdx.z, co = blockIdx.y;
    int idx = blockIdx.x * 256 + threadIdx.x;
    int y = idx >> 9, x = idx & 511;
    float s = bs[co];
    const float* ub = u + (size_t)b * CDIM * NPIX;
#pragma unroll
    for (int ky = 0; ky < 3; ky++) {
        int yy = y + ky - 1;
        if ((unsigned)yy >= 512u) continue;
        int sy = yy & 3, hy = yy >> 2;
#pragma unroll
        for (int kx = 0; kx < 3; kx++) {
            int xx = x + kx - 1;
            if ((unsigned)xx >= 512u) continue;
            int sx = xx & 3, hx = xx >> 2;
            const float* up = ub + (size_t)(sy * 4 + sx) * NPIX + hy * WW + hx;
#pragma unroll
            for (int ci = 0; ci < 8; ci++)
                s = fmaf(w[(co * 8 + ci) * 9 + ky * 3 + kx], up[(size_t)ci * 16 * NPIX], s);
        }
    }
    out[((size_t)b * 3 + co) * (512 * 512) + idx] = s;
}

// ---------------- launch ----------------
extern "C" void kernel_launch(void* const* d_in, const int* in_sizes, int n_in,
                              void* d_out, int out_size)
{
    const float* feats     = (const float*)d_in[0];
    const float* prj       = (const float*)d_in[1];
    const float* merge_w1  = (const float*)d_in[2];
    const float* merge_b1  = (const float*)d_in[3];
    const float* merge_wd  = (const float*)d_in[4];
    const float* merge_bd  = (const float*)d_in[5];
    const float* merge_w2  = (const float*)d_in[6];
    const float* merge_b2  = (const float*)d_in[7];
    const float* gru_w     = (const float*)d_in[8];
    const float* gru_bw    = (const float*)d_in[9];
    const float* alpha_w   = (const float*)d_in[10];
    const float* alpha_b   = (const float*)d_in[11];
    const float* up_w      = (const float*)d_in[12];
    const float* up_b      = (const float*)d_in[13];
    const float* outc_w    = (const float*)d_in[14];
    const float* outc_b    = (const float*)d_in[15];

    float *bufA, *bufB, *bufC, *hg, *alp, *pool, *u;
    u16 *wm1h, *wm1l, *wm2h, *wm2l, *wgh, *wgl, *wgbh, *wgbl, *wuph, *wupl;
    cudaGetSymbolAddress((void**)&bufA, g_bufA);
    cudaGetSymbolAddress((void**)&bufB, g_bufB);
    cudaGetSymbolAddress((void**)&bufC, g_bufC);
    cudaGetSymbolAddress((void**)&hg,   g_hg);
    cudaGetSymbolAddress((void**)&alp,  g_alp);
    cudaGetSymbolAddress((void**)&pool, g_pool);
    cudaGetSymbolAddress((void**)&u,    g_u);
    cudaGetSymbolAddress((void**)&wm1h, g_wm1h); cudaGetSymbolAddress((void**)&wm1l, g_wm1l);
    cudaGetSymbolAddress((void**)&wm2h, g_wm2h); cudaGetSymbolAddress((void**)&wm2l, g_wm2l);
    cudaGetSymbolAddress((void**)&wgh,  g_wgh);  cudaGetSymbolAddress((void**)&wgl,  g_wgl);
    cudaGetSymbolAddress((void**)&wgbh, g_wgbh); cudaGetSymbolAddress((void**)&wgbl, g_wgbl);
    cudaGetSymbolAddress((void**)&wuph, g_wuph); cudaGetSymbolAddress((void**)&wupl, g_wupl);

    cudaFuncSetAttribute(gemm_mma<256, 128, 1, true >, cudaFuncAttributeMaxDynamicSharedMemorySize, GSMEM);
    cudaFuncSetAttribute(gemm_mma<128, 128, 2, false>, cudaFuncAttributeMaxDynamicSharedMemorySize, GSMEM);
    cudaFuncSetAttribute(gemm_mma<128, 256, 0, false>, cudaFuncAttributeMaxDynamicSharedMemorySize, GSMEM);
    cudaFuncSetAttribute(gemm_mma<128, 128, 0, false>, cudaFuncAttributeMaxDynamicSharedMemorySize, GSMEM);
    cudaFuncSetAttribute(gemm_mma<256, 128, 1, true >, cudaFuncAttributePreferredSharedMemoryCarveout, 100);
    cudaFuncSetAttribute(gemm_mma<128, 128, 2, false>, cudaFuncAttributePreferredSharedMemoryCarveout, 100);
    cudaFuncSetAttribute(gemm_mma<128, 256, 0, false>, cudaFuncAttributePreferredSharedMemoryCarveout, 100);
    cudaFuncSetAttribute(gemm_mma<128, 128, 0, false>, cudaFuncAttributePreferredSharedMemoryCarveout, 100);

    // weight prep (one tiny kernel)
    prep_w_all<<<512, 256>>>(merge_w1, merge_w2, gru_w, gru_bw, up_w,
                             wm1h, wm1l, wm2h, wm2l, wgh, wgl, wgbh, wgbl, wuph, wupl);

    // merge1: 1x1 (2C->C) + GELU
    gemm_mma<256, 128, 1, true ><<<dim3(128, 1, BVI), 256, GSMEM>>>(
        feats, prj, wm1h, wm1l, merge_b1, nullptr, bufA);
    // depthwise 3x3 + GELU
    dw3x3<<<dim3(64, CDIM, BVI), 256>>>(bufA, merge_wd, merge_bd, bufB);
    // merge2: 1x1 (C->C) + bias + residual
    gemm_mma<128, 128, 2, false><<<dim3(128, 1, BVI), 256, GSMEM>>>(
        bufB, nullptr, wm2h, wm2l, merge_b2, feats, bufC);
    // fwd GRU linear (C->2C)
    gemm_mma<128, 256, 0, false><<<dim3(128, 2, BVI), 256, GSMEM>>>(
        bufC, nullptr, wgh, wgl, nullptr, nullptr, hg);
    gru_scan<<<dim3(64, CDIM, NB), 256>>>(hg, bufA);
    // bwd GRU linear (H-flips cancel -> forward scan)
    gemm_mma<128, 256, 0, false><<<dim3(128, 2, BVI), 256, GSMEM>>>(
        bufA, nullptr, wgbh, wgbl, nullptr, nullptr, hg);
    gru_scan<<<dim3(64, CDIM, NB), 256>>>(hg, bufB);
    // alpha conv + softmax pool
    alpha_conv<<<dim3(64, 1, BVI), 256>>>(bufB, alpha_w, alpha_b, alp);
    pool_k<<<dim3(64, 1, NB), 256>>>(bufB, alp, pool);
    // up 1x1 conv
    gemm_mma<128, 128, 0, false><<<dim3(128, 1, NB), 256, GSMEM>>>(
        pool, nullptr, wuph, wupl, up_b, nullptr, u);
    // pixel shuffle + outc 3x3
    outc_k<<<dim3(1024, 3, NB), 256>>>(u, outc_w, outc_b, (float*)d_out);
}